// round 2
// baseline (speedup 1.0000x reference)
#include <cuda_runtime.h>
#include <float.h>

#define N_NODES 50000
#define N_EDGES 800000
#define F 128
#define L_LAYERS 3
#define G_GROUPS 256
#define T_OUT 10
#define LF (L_LAYERS * F)   // 384

// ---------------- scratch (device globals; no allocation allowed) ----------
__device__ __align__(16) float g_agg[N_NODES * F];        // 25.6 MB
__device__ __align__(16) float g_hc[N_NODES * LF];        // 76.8 MB (concat of 3 layer outputs)
__device__ __align__(16) float g_inv_deg[N_NODES];
__device__ __align__(16) int   g_deg[N_NODES];
__device__ __align__(16) float g_pooled[G_GROUPS * LF];

// ---------------- zeroing -------------------------------------------------
__global__ void zero_agg_kernel() {
    int i = blockIdx.x * blockDim.x + threadIdx.x;
    float4* p = reinterpret_cast<float4*>(g_agg);
    if (i < (N_NODES * F) / 4) p[i] = make_float4(0.f, 0.f, 0.f, 0.f);
}

__global__ void zero_deg_kernel() {
    int i = blockIdx.x * blockDim.x + threadIdx.x;
    if (i < N_NODES) g_deg[i] = 0;
}

// ---------------- degree --------------------------------------------------
__global__ void deg_kernel(const int* __restrict__ ei) {
    int e = blockIdx.x * blockDim.x + threadIdx.x;
    if (e < N_EDGES) {
        int d = ei[N_EDGES + e];
        if (d >= 0 && d < N_NODES) atomicAdd(&g_deg[d], 1);
    }
}

__global__ void inv_deg_kernel() {
    int i = blockIdx.x * blockDim.x + threadIdx.x;
    if (i < N_NODES) {
        int d = g_deg[i];
        g_inv_deg[i] = d > 0 ? 1.0f / (float)d : 0.0f;
    }
}

// ---------------- edge scatter: agg[dst] += h[src] ------------------------
// One warp per edge; lane c handles 16B chunk c of the 512B feature row.
__global__ void scatter_kernel(const int* __restrict__ ei,
                               const float* __restrict__ x, int layer) {
    int gtid = blockIdx.x * blockDim.x + threadIdx.x;
    int warp = gtid >> 5;
    int lane = gtid & 31;
    if (warp >= N_EDGES) return;

    int s = 0, d = 0;
    if (lane == 0) {
        s = ei[warp];
        d = ei[N_EDGES + warp];
    }
    int src = __shfl_sync(0xFFFFFFFFu, s, 0);
    int dst = __shfl_sync(0xFFFFFFFFu, d, 0);
    if ((unsigned)src >= N_NODES || (unsigned)dst >= N_NODES) return;

    const float* h;
    int stride;
    if (layer == 0) { h = x; stride = F; }
    else            { h = g_hc + (layer - 1) * F; stride = LF; }

    float4 v = *reinterpret_cast<const float4*>(h + (size_t)src * stride + lane * 4);
    float* a = g_agg + (size_t)dst * F + lane * 4;
    atomicAdd(a + 0, v.x);
    atomicAdd(a + 1, v.y);
    atomicAdd(a + 2, v.z);
    atomicAdd(a + 3, v.w);
}

// ---------------- fused SAGE GEMM ----------------------------------------
// out[n, :] = (agg[n,:] * inv_deg[n]) @ Wl^T + h[n,:] @ Wr^T + bl
// BM=128, BN=128(=F), BK=32, 256 threads, 8x8 micro-tile per thread.
#define BK 32
#define SPAD 132   // padded smem row

__global__ void __launch_bounds__(256) sage_gemm_kernel(
    const float* __restrict__ x, int layer,
    const float* __restrict__ Wl_all, const float* __restrict__ Wr_all,
    const float* __restrict__ bl_all) {

    __shared__ float As[BK][SPAD];
    __shared__ float Bs[BK][SPAD];

    const float* Wl = Wl_all + layer * F * F;
    const float* Wr = Wr_all + layer * F * F;
    const float* bias = bl_all + layer * F;

    const float* h;
    int strideH;
    if (layer == 0) { h = x; strideH = F; }
    else            { h = g_hc + (layer - 1) * F; strideH = LF; }

    int row0 = blockIdx.x * 128;
    int tid = threadIdx.x;
    int tr = tid >> 4;       // 0..15  (row group)
    int tc = tid & 15;       // 0..15  (col group)

    float acc[8][8];
#pragma unroll
    for (int y = 0; y < 8; ++y)
#pragma unroll
        for (int xk = 0; xk < 8; ++xk) acc[y][xk] = 0.f;

    for (int pass = 0; pass < 2; ++pass) {
        const float* A = pass ? h : g_agg;
        int sA = pass ? strideH : F;
        const float* W = pass ? Wr : Wl;

        for (int k0 = 0; k0 < F; k0 += BK) {
            // load A tile (transposed into As[k][m]); scale by inv_deg on pass 0
#pragma unroll
            for (int i = 0; i < 4; ++i) {
                int t4 = tid + i * 256;      // 0..1023 float4 slots
                int m = t4 >> 3;             // 0..127
                int kk = (t4 & 7) * 4;       // 0,4,...,28
                int grow = row0 + m;
                float4 v = make_float4(0.f, 0.f, 0.f, 0.f);
                if (grow < N_NODES) {
                    v = *reinterpret_cast<const float4*>(A + (size_t)grow * sA + k0 + kk);
                    if (pass == 0) {
                        float s = g_inv_deg[grow];
                        v.x *= s; v.y *= s; v.z *= s; v.w *= s;
                    }
                }
                As[kk + 0][m] = v.x;
                As[kk + 1][m] = v.y;
                As[kk + 2][m] = v.z;
                As[kk + 3][m] = v.w;
            }
            // load B tile: Bs[k][j] = W[j*F + k0 + k]
#pragma unroll
            for (int i = 0; i < 4; ++i) {
                int t4 = tid + i * 256;
                int j = t4 >> 3;
                int kk = (t4 & 7) * 4;
                float4 w = *reinterpret_cast<const float4*>(W + j * F + k0 + kk);
                Bs[kk + 0][j] = w.x;
                Bs[kk + 1][j] = w.y;
                Bs[kk + 2][j] = w.z;
                Bs[kk + 3][j] = w.w;
            }
            __syncthreads();

#pragma unroll
            for (int k = 0; k < BK; ++k) {
                float a[8], b[8];
#pragma unroll
                for (int y = 0; y < 8; ++y) a[y] = As[k][tr * 8 + y];
#pragma unroll
                for (int xk = 0; xk < 8; ++xk) b[xk] = Bs[k][tc * 8 + xk];
#pragma unroll
                for (int y = 0; y < 8; ++y)
#pragma unroll
                    for (int xk = 0; xk < 8; ++xk)
                        acc[y][xk] += a[y] * b[xk];
            }
            __syncthreads();
        }
    }

    // epilogue: + bias, write into hc[:, layer*F : (layer+1)*F]
    float bvals[8];
#pragma unroll
    for (int xk = 0; xk < 8; ++xk) bvals[xk] = bias[tc * 8 + xk];

    float* out = g_hc + layer * F;
#pragma unroll
    for (int y = 0; y < 8; ++y) {
        int grow = row0 + tr * 8 + y;
        if (grow < N_NODES) {
            float4 o0, o1;
            o0.x = acc[y][0] + bvals[0]; o0.y = acc[y][1] + bvals[1];
            o0.z = acc[y][2] + bvals[2]; o0.w = acc[y][3] + bvals[3];
            o1.x = acc[y][4] + bvals[4]; o1.y = acc[y][5] + bvals[5];
            o1.z = acc[y][6] + bvals[6]; o1.w = acc[y][7] + bvals[7];
            *reinterpret_cast<float4*>(out + (size_t)grow * LF + tc * 8)     = o0;
            *reinterpret_cast<float4*>(out + (size_t)grow * LF + tc * 8 + 4) = o1;
        }
    }
}

// ---------------- segment max pool over sorted batch ----------------------
__global__ void pool_kernel(const int* __restrict__ batch) {
    int g = blockIdx.x;          // 0..G-1
    int col = threadIdx.x;       // 0..LF-1 (384 threads)

    // lower_bound(batch, g) and lower_bound(batch, g+1)
    int lo = 0, hi = N_NODES;
    while (lo < hi) { int mid = (lo + hi) >> 1; if (batch[mid] < g) lo = mid + 1; else hi = mid; }
    int start = lo;
    hi = N_NODES;
    while (lo < hi) { int mid = (lo + hi) >> 1; if (batch[mid] < g + 1) lo = mid + 1; else hi = mid; }
    int end = lo;

    float m = -FLT_MAX;
    for (int r = start; r < end; ++r)
        m = fmaxf(m, g_hc[(size_t)r * LF + col]);
    g_pooled[g * LF + col] = m;
}

// ---------------- final MLP: relu(pooled@W1^T+b1)@W2^T+b2 -----------------
__global__ void mlp_kernel(const float* __restrict__ W1, const float* __restrict__ b1,
                           const float* __restrict__ W2, const float* __restrict__ b2,
                           float* __restrict__ out) {
    int g = blockIdx.x;          // 0..G-1
    int tid = threadIdx.x;       // 0..127

    __shared__ __align__(16) float p[LF];
    __shared__ __align__(16) float z[F];

    for (int i = tid; i < LF; i += F) p[i] = g_pooled[g * LF + i];
    __syncthreads();

    float s = b1[tid];
    const float* w = W1 + tid * LF;
#pragma unroll 4
    for (int k = 0; k < LF; k += 4) {
        float4 wv = *reinterpret_cast<const float4*>(w + k);
        s += wv.x * p[k] + wv.y * p[k + 1] + wv.z * p[k + 2] + wv.w * p[k + 3];
    }
    z[tid] = fmaxf(s, 0.f);
    __syncthreads();

    if (tid < T_OUT) {
        float o = b2[tid];
        const float* w2 = W2 + tid * F;
#pragma unroll 4
        for (int k = 0; k < F; k += 4) {
            float4 wv = *reinterpret_cast<const float4*>(w2 + k);
            o += wv.x * z[k] + wv.y * z[k + 1] + wv.z * z[k + 2] + wv.w * z[k + 3];
        }
        out[g * T_OUT + tid] = o;
    }
}

// ---------------- launch --------------------------------------------------
extern "C" void kernel_launch(void* const* d_in, const int* in_sizes, int n_in,
                              void* d_out, int out_size) {
    const float* x     = (const float*)d_in[0];
    const int*   ei    = (const int*)d_in[1];   // int64 in reference -> delivered as int32
    const int*   batch = (const int*)d_in[2];   // int64 in reference -> delivered as int32
    const float* Wl    = (const float*)d_in[3];
    const float* bl    = (const float*)d_in[4];
    const float* Wr    = (const float*)d_in[5];
    const float* W1    = (const float*)d_in[6];
    const float* b1    = (const float*)d_in[7];
    const float* W2    = (const float*)d_in[8];
    const float* b2    = (const float*)d_in[9];
    float* out = (float*)d_out;

    // degree + inverse degree
    zero_deg_kernel<<<(N_NODES + 255) / 256, 256>>>();
    deg_kernel<<<(N_EDGES + 255) / 256, 256>>>(ei);
    inv_deg_kernel<<<(N_NODES + 255) / 256, 256>>>();

    const int scatter_blocks = (N_EDGES * 32) / 256;          // 100000
    const int zero_blocks    = (N_NODES * F / 4 + 255) / 256; // 6250
    const int gemm_blocks    = (N_NODES + 127) / 128;         // 391

    for (int layer = 0; layer < L_LAYERS; ++layer) {
        zero_agg_kernel<<<zero_blocks, 256>>>();
        scatter_kernel<<<scatter_blocks, 256>>>(ei, x, layer);
        sage_gemm_kernel<<<gemm_blocks, 256>>>(x, layer, Wl, Wr, bl);
    }

    pool_kernel<<<G_GROUPS, LF>>>(batch);
    mlp_kernel<<<G_GROUPS, F>>>(W1, b1, W2, b2, out);
}

// round 4
// speedup vs baseline: 2.1051x; 2.1051x over previous
#include <cuda_runtime.h>
#include <float.h>

#define N_NODES 50000
#define N_EDGES 800000
#define F 128
#define L_LAYERS 3
#define G_GROUPS 256
#define T_OUT 10
#define LF (L_LAYERS * F)   // 384

// ---------------- scratch (device globals; no allocation allowed) ----------
__device__ __align__(16) float g_agg[N_NODES * F];        // 25.6 MB (mean-aggregated, pre-scaled)
__device__ __align__(16) float g_hc[N_NODES * LF];        // 76.8 MB (concat of 3 layer outputs)
__device__ __align__(16) int   g_deg[N_NODES];
__device__ __align__(16) int   g_row_start[N_NODES + 1];  // CSR offsets (by dst)
__device__ __align__(16) int   g_cursor[N_NODES];
__device__ __align__(16) int   g_csr_src[N_EDGES];        // src ids grouped by dst
__device__ __align__(16) float g_pooled[G_GROUPS * LF];

// ---------------- CSR build -----------------------------------------------
__global__ void zero_deg_kernel() {
    int i = blockIdx.x * blockDim.x + threadIdx.x;
    if (i < N_NODES) g_deg[i] = 0;
}

__global__ void deg_kernel(const int* __restrict__ ei) {
    int e = blockIdx.x * blockDim.x + threadIdx.x;
    if (e < N_EDGES) {
        int d = ei[N_EDGES + e];
        if ((unsigned)d < N_NODES) atomicAdd(&g_deg[d], 1);
    }
}

// single-block exclusive scan over g_deg -> g_row_start (+ copy to g_cursor)
__global__ void scan_kernel() {
    __shared__ int s[1024];
    __shared__ int carry;
    int tid = threadIdx.x;
    if (tid == 0) carry = 0;
    __syncthreads();

    for (int base = 0; base < N_NODES; base += 1024) {
        int idx = base + tid;
        int v = (idx < N_NODES) ? g_deg[idx] : 0;
        s[tid] = v;
        __syncthreads();
#pragma unroll
        for (int off = 1; off < 1024; off <<= 1) {
            int t = (tid >= off) ? s[tid - off] : 0;
            __syncthreads();
            s[tid] += t;
            __syncthreads();
        }
        if (idx < N_NODES) {
            int excl = carry + s[tid] - v;
            g_row_start[idx] = excl;
            g_cursor[idx] = excl;
        }
        __syncthreads();
        if (tid == 0) carry += s[1023];
        __syncthreads();
    }
    if (tid == 0) g_row_start[N_NODES] = N_EDGES;
}

__global__ void fill_kernel(const int* __restrict__ ei) {
    int e = blockIdx.x * blockDim.x + threadIdx.x;
    if (e < N_EDGES) {
        int src = ei[e];
        int dst = ei[N_EDGES + e];
        if ((unsigned)src < N_NODES && (unsigned)dst < N_NODES) {
            int pos = atomicAdd(&g_cursor[dst], 1);
            g_csr_src[pos] = src;
        }
    }
}

// ---------------- per-node warp gather: agg[n] = mean_{s in N(n)} h[s] ----
// One warp per dst node; lane c owns 16B chunk c of the 512B feature row.
__global__ void __launch_bounds__(256) gather_kernel(const float* __restrict__ x, int layer) {
    int gtid = blockIdx.x * blockDim.x + threadIdx.x;
    int node = gtid >> 5;
    int lane = gtid & 31;
    if (node >= N_NODES) return;

    const float* h;
    int stride;
    if (layer == 0) { h = x; stride = F; }
    else            { h = g_hc + (layer - 1) * F; stride = LF; }

    int start = g_row_start[node];
    int end   = g_row_start[node + 1];

    float4 acc = make_float4(0.f, 0.f, 0.f, 0.f);
    int i = start;
    for (; i + 4 <= end; i += 4) {
        int s0 = g_csr_src[i + 0];
        int s1 = g_csr_src[i + 1];
        int s2 = g_csr_src[i + 2];
        int s3 = g_csr_src[i + 3];
        float4 v0 = *reinterpret_cast<const float4*>(h + (size_t)s0 * stride + lane * 4);
        float4 v1 = *reinterpret_cast<const float4*>(h + (size_t)s1 * stride + lane * 4);
        float4 v2 = *reinterpret_cast<const float4*>(h + (size_t)s2 * stride + lane * 4);
        float4 v3 = *reinterpret_cast<const float4*>(h + (size_t)s3 * stride + lane * 4);
        acc.x += v0.x + v1.x + v2.x + v3.x;
        acc.y += v0.y + v1.y + v2.y + v3.y;
        acc.z += v0.z + v1.z + v2.z + v3.z;
        acc.w += v0.w + v1.w + v2.w + v3.w;
    }
    for (; i < end; ++i) {
        int s0 = g_csr_src[i];
        float4 v0 = *reinterpret_cast<const float4*>(h + (size_t)s0 * stride + lane * 4);
        acc.x += v0.x; acc.y += v0.y; acc.z += v0.z; acc.w += v0.w;
    }

    int d = end - start;
    float inv = d > 0 ? 1.0f / (float)d : 0.0f;
    acc.x *= inv; acc.y *= inv; acc.z *= inv; acc.w *= inv;
    *reinterpret_cast<float4*>(g_agg + (size_t)node * F + lane * 4) = acc;
}

// ---------------- fused SAGE GEMM ----------------------------------------
// out[n, :] = agg[n,:] @ Wl^T + h[n,:] @ Wr^T + bl   (agg already mean-scaled)
// BM=128, BN=128(=F), BK=32, 256 threads, 8x8 micro-tile per thread.
#define BK 32
#define SPAD 132   // padded smem row

__global__ void __launch_bounds__(256) sage_gemm_kernel(
    const float* __restrict__ x, int layer,
    const float* __restrict__ Wl_all, const float* __restrict__ Wr_all,
    const float* __restrict__ bl_all) {

    __shared__ float As[BK][SPAD];
    __shared__ float Bs[BK][SPAD];

    const float* Wl = Wl_all + layer * F * F;
    const float* Wr = Wr_all + layer * F * F;
    const float* bias = bl_all + layer * F;

    const float* h;
    int strideH;
    if (layer == 0) { h = x; strideH = F; }
    else            { h = g_hc + (layer - 1) * F; strideH = LF; }

    int row0 = blockIdx.x * 128;
    int tid = threadIdx.x;
    int tr = tid >> 4;       // 0..15  (row group)
    int tc = tid & 15;       // 0..15  (col group)

    float acc[8][8];
#pragma unroll
    for (int y = 0; y < 8; ++y)
#pragma unroll
        for (int xk = 0; xk < 8; ++xk) acc[y][xk] = 0.f;

    for (int pass = 0; pass < 2; ++pass) {
        const float* A = pass ? h : g_agg;
        int sA = pass ? strideH : F;
        const float* W = pass ? Wr : Wl;

        for (int k0 = 0; k0 < F; k0 += BK) {
            // load A tile (transposed into As[k][m])
#pragma unroll
            for (int i = 0; i < 4; ++i) {
                int t4 = tid + i * 256;      // 0..1023 float4 slots
                int m = t4 >> 3;             // 0..127
                int kk = (t4 & 7) * 4;       // 0,4,...,28
                int grow = row0 + m;
                float4 v = make_float4(0.f, 0.f, 0.f, 0.f);
                if (grow < N_NODES)
                    v = *reinterpret_cast<const float4*>(A + (size_t)grow * sA + k0 + kk);
                As[kk + 0][m] = v.x;
                As[kk + 1][m] = v.y;
                As[kk + 2][m] = v.z;
                As[kk + 3][m] = v.w;
            }
            // load B tile: Bs[k][j] = W[j*F + k0 + k]
#pragma unroll
            for (int i = 0; i < 4; ++i) {
                int t4 = tid + i * 256;
                int j = t4 >> 3;
                int kk = (t4 & 7) * 4;
                float4 w = *reinterpret_cast<const float4*>(W + j * F + k0 + kk);
                Bs[kk + 0][j] = w.x;
                Bs[kk + 1][j] = w.y;
                Bs[kk + 2][j] = w.z;
                Bs[kk + 3][j] = w.w;
            }
            __syncthreads();

#pragma unroll
            for (int k = 0; k < BK; ++k) {
                float a[8], b[8];
#pragma unroll
                for (int y = 0; y < 8; ++y) a[y] = As[k][tr * 8 + y];
#pragma unroll
                for (int xk = 0; xk < 8; ++xk) b[xk] = Bs[k][tc * 8 + xk];
#pragma unroll
                for (int y = 0; y < 8; ++y)
#pragma unroll
                    for (int xk = 0; xk < 8; ++xk)
                        acc[y][xk] += a[y] * b[xk];
            }
            __syncthreads();
        }
    }

    // epilogue: + bias, write into hc[:, layer*F : (layer+1)*F]
    float bvals[8];
#pragma unroll
    for (int xk = 0; xk < 8; ++xk) bvals[xk] = bias[tc * 8 + xk];

    float* out = g_hc + layer * F;
#pragma unroll
    for (int y = 0; y < 8; ++y) {
        int grow = row0 + tr * 8 + y;
        if (grow < N_NODES) {
            float4 o0, o1;
            o0.x = acc[y][0] + bvals[0]; o0.y = acc[y][1] + bvals[1];
            o0.z = acc[y][2] + bvals[2]; o0.w = acc[y][3] + bvals[3];
            o1.x = acc[y][4] + bvals[4]; o1.y = acc[y][5] + bvals[5];
            o1.z = acc[y][6] + bvals[6]; o1.w = acc[y][7] + bvals[7];
            *reinterpret_cast<float4*>(out + (size_t)grow * LF + tc * 8)     = o0;
            *reinterpret_cast<float4*>(out + (size_t)grow * LF + tc * 8 + 4) = o1;
        }
    }
}

// ---------------- segment max pool over sorted batch ----------------------
__global__ void pool_kernel(const int* __restrict__ batch) {
    int g = blockIdx.x;          // 0..G-1
    int col = threadIdx.x;       // 0..LF-1 (384 threads)

    int lo = 0, hi = N_NODES;
    while (lo < hi) { int mid = (lo + hi) >> 1; if (batch[mid] < g) lo = mid + 1; else hi = mid; }
    int start = lo;
    hi = N_NODES;
    while (lo < hi) { int mid = (lo + hi) >> 1; if (batch[mid] < g + 1) lo = mid + 1; else hi = mid; }
    int end = lo;

    float m = -FLT_MAX;
    for (int r = start; r < end; ++r)
        m = fmaxf(m, g_hc[(size_t)r * LF + col]);
    g_pooled[g * LF + col] = m;
}

// ---------------- final MLP: relu(pooled@W1^T+b1)@W2^T+b2 -----------------
__global__ void mlp_kernel(const float* __restrict__ W1, const float* __restrict__ b1,
                           const float* __restrict__ W2, const float* __restrict__ b2,
                           float* __restrict__ out) {
    int g = blockIdx.x;          // 0..G-1
    int tid = threadIdx.x;       // 0..127

    __shared__ __align__(16) float p[LF];
    __shared__ __align__(16) float z[F];

    for (int i = tid; i < LF; i += F) p[i] = g_pooled[g * LF + i];
    __syncthreads();

    float s = b1[tid];
    const float* w = W1 + tid * LF;
#pragma unroll 4
    for (int k = 0; k < LF; k += 4) {
        float4 wv = *reinterpret_cast<const float4*>(w + k);
        s += wv.x * p[k] + wv.y * p[k + 1] + wv.z * p[k + 2] + wv.w * p[k + 3];
    }
    z[tid] = fmaxf(s, 0.f);
    __syncthreads();

    if (tid < T_OUT) {
        float o = b2[tid];
        const float* w2 = W2 + tid * F;
#pragma unroll 4
        for (int k = 0; k < F; k += 4) {
            float4 wv = *reinterpret_cast<const float4*>(w2 + k);
            o += wv.x * z[k] + wv.y * z[k + 1] + wv.z * z[k + 2] + wv.w * z[k + 3];
        }
        out[g * T_OUT + tid] = o;
    }
}

// ---------------- launch --------------------------------------------------
extern "C" void kernel_launch(void* const* d_in, const int* in_sizes, int n_in,
                              void* d_out, int out_size) {
    const float* x     = (const float*)d_in[0];
    const int*   ei    = (const int*)d_in[1];
    const int*   batch = (const int*)d_in[2];
    const float* Wl    = (const float*)d_in[3];
    const float* bl    = (const float*)d_in[4];
    const float* Wr    = (const float*)d_in[5];
    const float* W1    = (const float*)d_in[6];
    const float* b1    = (const float*)d_in[7];
    const float* W2    = (const float*)d_in[8];
    const float* b2    = (const float*)d_in[9];
    float* out = (float*)d_out;

    // CSR build (by dst)
    zero_deg_kernel<<<(N_NODES + 255) / 256, 256>>>();
    deg_kernel<<<(N_EDGES + 255) / 256, 256>>>(ei);
    scan_kernel<<<1, 1024>>>();
    fill_kernel<<<(N_EDGES + 255) / 256, 256>>>(ei);

    const int gather_blocks = (N_NODES * 32 + 255) / 256;  // 6250
    const int gemm_blocks   = (N_NODES + 127) / 128;       // 391

    for (int layer = 0; layer < L_LAYERS; ++layer) {
        gather_kernel<<<gather_blocks, 256>>>(x, layer);
        sage_gemm_kernel<<<gemm_blocks, 256>>>(x, layer, Wl, Wr, bl);
    }

    pool_kernel<<<G_GROUPS, LF>>>(batch);
    mlp_kernel<<<G_GROUPS, F>>>(W1, b1, W2, b2, out);
}

// round 5
// speedup vs baseline: 2.9679x; 1.4098x over previous
#include <cuda_runtime.h>
#include <float.h>
#include <stdint.h>

#define N_NODES 50000
#define N_EDGES 800000
#define F 128
#define L_LAYERS 3
#define G_GROUPS 256
#define T_OUT 10
#define LF (L_LAYERS * F)   // 384

// ---------------- scratch (device globals; no allocation allowed) ----------
__device__ __align__(16) float g_agg[N_NODES * F];        // mean-aggregated (pre-scaled)
__device__ __align__(16) float g_hc[N_NODES * LF];        // concat of 3 layer outputs
__device__ __align__(16) int   g_deg[N_NODES];
__device__ __align__(16) int   g_row_start[N_NODES + 1];  // CSR offsets (by dst)
__device__ __align__(16) int   g_cursor[N_NODES];
__device__ __align__(16) int   g_csr_src[N_EDGES];        // src ids grouped by dst
__device__ __align__(16) float g_pooled[G_GROUPS * LF];

// ---------------- CSR build -----------------------------------------------
__global__ void zero_deg_kernel() {
    int i = blockIdx.x * blockDim.x + threadIdx.x;
    if (i < N_NODES) g_deg[i] = 0;
}

__global__ void deg_kernel(const int* __restrict__ ei) {
    int e = blockIdx.x * blockDim.x + threadIdx.x;
    if (e < N_EDGES) {
        int d = ei[N_EDGES + e];
        if ((unsigned)d < N_NODES) atomicAdd(&g_deg[d], 1);
    }
}

__global__ void scan_kernel() {
    __shared__ int s[1024];
    __shared__ int carry;
    int tid = threadIdx.x;
    if (tid == 0) carry = 0;
    __syncthreads();

    for (int base = 0; base < N_NODES; base += 1024) {
        int idx = base + tid;
        int v = (idx < N_NODES) ? g_deg[idx] : 0;
        s[tid] = v;
        __syncthreads();
#pragma unroll
        for (int off = 1; off < 1024; off <<= 1) {
            int t = (tid >= off) ? s[tid - off] : 0;
            __syncthreads();
            s[tid] += t;
            __syncthreads();
        }
        if (idx < N_NODES) {
            int excl = carry + s[tid] - v;
            g_row_start[idx] = excl;
            g_cursor[idx] = excl;
        }
        __syncthreads();
        if (tid == 0) carry += s[1023];
        __syncthreads();
    }
    if (tid == 0) g_row_start[N_NODES] = N_EDGES;
}

__global__ void fill_kernel(const int* __restrict__ ei) {
    int e = blockIdx.x * blockDim.x + threadIdx.x;
    if (e < N_EDGES) {
        int src = ei[e];
        int dst = ei[N_EDGES + e];
        if ((unsigned)src < N_NODES && (unsigned)dst < N_NODES) {
            int pos = atomicAdd(&g_cursor[dst], 1);
            g_csr_src[pos] = src;
        }
    }
}

// ---------------- per-node warp gather: agg[n] = mean_{s in N(n)} h[s] ----
__global__ void __launch_bounds__(256) gather_kernel(const float* __restrict__ x, int layer) {
    int gtid = blockIdx.x * blockDim.x + threadIdx.x;
    int node = gtid >> 5;
    int lane = gtid & 31;
    if (node >= N_NODES) return;

    const float* h;
    int stride;
    if (layer == 0) { h = x; stride = F; }
    else            { h = g_hc + (layer - 1) * F; stride = LF; }

    int start = g_row_start[node];
    int end   = g_row_start[node + 1];

    float4 acc = make_float4(0.f, 0.f, 0.f, 0.f);
    int i = start;
    for (; i + 4 <= end; i += 4) {
        int s0 = g_csr_src[i + 0];
        int s1 = g_csr_src[i + 1];
        int s2 = g_csr_src[i + 2];
        int s3 = g_csr_src[i + 3];
        float4 v0 = *reinterpret_cast<const float4*>(h + (size_t)s0 * stride + lane * 4);
        float4 v1 = *reinterpret_cast<const float4*>(h + (size_t)s1 * stride + lane * 4);
        float4 v2 = *reinterpret_cast<const float4*>(h + (size_t)s2 * stride + lane * 4);
        float4 v3 = *reinterpret_cast<const float4*>(h + (size_t)s3 * stride + lane * 4);
        acc.x += v0.x + v1.x + v2.x + v3.x;
        acc.y += v0.y + v1.y + v2.y + v3.y;
        acc.z += v0.z + v1.z + v2.z + v3.z;
        acc.w += v0.w + v1.w + v2.w + v3.w;
    }
    for (; i < end; ++i) {
        int s0 = g_csr_src[i];
        float4 v0 = *reinterpret_cast<const float4*>(h + (size_t)s0 * stride + lane * 4);
        acc.x += v0.x; acc.y += v0.y; acc.z += v0.z; acc.w += v0.w;
    }

    int d = end - start;
    float inv = d > 0 ? 1.0f / (float)d : 0.0f;
    acc.x *= inv; acc.y *= inv; acc.z *= inv; acc.w *= inv;
    *reinterpret_cast<float4*>(g_agg + (size_t)node * F + lane * 4) = acc;
}

// ---------------- TF32 tensor-core fused SAGE GEMM ------------------------
// out[n,:] = agg[n,:] @ Wl^T + h[n,:] @ Wr^T + bl
// Block tile 128x128, 8 warps (2x4), warp tile 64x32, mma.m16n8k8.tf32.
#define BKT 32
#define ASTRIDE 36    // words; 4g+tg bank pattern -> conflict-free frag loads
#define BSTRIDE 136   // words; 8tg+g bank pattern -> conflict-free frag loads

__device__ __forceinline__ uint32_t f2tf32(float f) {
    uint32_t u;
    asm volatile("cvt.rna.tf32.f32 %0, %1;" : "=r"(u) : "f"(f));
    return u;
}

__device__ __forceinline__ void mma_tf32(float* d,
                                         const uint32_t* a, const uint32_t* b) {
    asm volatile(
        "mma.sync.aligned.m16n8k8.row.col.f32.tf32.tf32.f32 "
        "{%0,%1,%2,%3}, {%4,%5,%6,%7}, {%8,%9}, {%0,%1,%2,%3};\n"
        : "+f"(d[0]), "+f"(d[1]), "+f"(d[2]), "+f"(d[3])
        : "r"(a[0]), "r"(a[1]), "r"(a[2]), "r"(a[3]),
          "r"(b[0]), "r"(b[1]));
}

__global__ void __launch_bounds__(256) sage_gemm_tf32_kernel(
    const float* __restrict__ x, int layer,
    const float* __restrict__ Wl_all, const float* __restrict__ Wr_all,
    const float* __restrict__ bl_all) {

    __shared__ uint32_t As[128 * ASTRIDE];   // 18.0 KB
    __shared__ uint32_t Bs[BKT * BSTRIDE];   // 17.0 KB

    const float* Wl = Wl_all + layer * F * F;
    const float* Wr = Wr_all + layer * F * F;

    const float* h;
    int strideH;
    if (layer == 0) { h = x; strideH = F; }
    else            { h = g_hc + (layer - 1) * F; strideH = LF; }

    int tid  = threadIdx.x;
    int warp = tid >> 5;
    int lane = tid & 31;
    int wm = warp >> 2;          // 0..1
    int wn = warp & 3;           // 0..3
    int grp = lane >> 2;         // 0..7
    int tg  = lane & 3;          // 0..3

    int row0 = blockIdx.x * 128;

    float acc[4][4][4];
#pragma unroll
    for (int mf = 0; mf < 4; ++mf)
#pragma unroll
        for (int nf = 0; nf < 4; ++nf)
#pragma unroll
            for (int r = 0; r < 4; ++r) acc[mf][nf][r] = 0.f;

    for (int pass = 0; pass < 2; ++pass) {
        const float* A = pass ? h : g_agg;
        int sA = pass ? strideH : F;
        const float* W = pass ? Wr : Wl;

        for (int k0 = 0; k0 < F; k0 += BKT) {
            __syncthreads();   // protect previous stage's frag reads
            // ---- A stage: coalesced row loads, transposed-none store ----
#pragma unroll
            for (int i = 0; i < 4; ++i) {
                int t4 = tid + i * 256;          // 0..1023
                int m  = t4 >> 3;                // 0..127
                int c4 = (t4 & 7) * 4;           // 0..28
                float4 v = make_float4(0.f, 0.f, 0.f, 0.f);
                int grow = row0 + m;
                if (grow < N_NODES)
                    v = *reinterpret_cast<const float4*>(A + (size_t)grow * sA + k0 + c4);
                uint32_t* dstp = &As[m * ASTRIDE + c4];
                dstp[0] = f2tf32(v.x);
                dstp[1] = f2tf32(v.y);
                dstp[2] = f2tf32(v.z);
                dstp[3] = f2tf32(v.w);
            }
            // ---- B stage: Bs[k][j] = W[j*F + k0 + k]; j varies per-lane
            //      (conflict-free STS; W is 64KB, L1/L2-resident) ----
#pragma unroll
            for (int i = 0; i < 4; ++i) {
                int t4 = tid + i * 256;
                int j  = t4 & 127;
                int c4 = (t4 >> 7) * 4;          // 0..28
                float4 w = *reinterpret_cast<const float4*>(W + j * F + k0 + c4);
                Bs[(c4 + 0) * BSTRIDE + j] = f2tf32(w.x);
                Bs[(c4 + 1) * BSTRIDE + j] = f2tf32(w.y);
                Bs[(c4 + 2) * BSTRIDE + j] = f2tf32(w.z);
                Bs[(c4 + 3) * BSTRIDE + j] = f2tf32(w.w);
            }
            __syncthreads();

#pragma unroll
            for (int kk = 0; kk < BKT; kk += 8) {
                uint32_t afr[4][4], bfr[4][2];
#pragma unroll
                for (int mf = 0; mf < 4; ++mf) {
                    int mr = wm * 64 + mf * 16 + grp;
                    afr[mf][0] = As[mr * ASTRIDE + kk + tg];
                    afr[mf][1] = As[(mr + 8) * ASTRIDE + kk + tg];
                    afr[mf][2] = As[mr * ASTRIDE + kk + tg + 4];
                    afr[mf][3] = As[(mr + 8) * ASTRIDE + kk + tg + 4];
                }
#pragma unroll
                for (int nf = 0; nf < 4; ++nf) {
                    int nc = wn * 32 + nf * 8 + grp;
                    bfr[nf][0] = Bs[(kk + tg) * BSTRIDE + nc];
                    bfr[nf][1] = Bs[(kk + tg + 4) * BSTRIDE + nc];
                }
#pragma unroll
                for (int mf = 0; mf < 4; ++mf)
#pragma unroll
                    for (int nf = 0; nf < 4; ++nf)
                        mma_tf32(acc[mf][nf], afr[mf], bfr[nf]);
            }
        }
    }

    // ---- epilogue: + bias, write hc[:, layer*F : (layer+1)*F] ----
    const float* bias = bl_all + layer * F;
    float* outp = g_hc + layer * F;
#pragma unroll
    for (int mf = 0; mf < 4; ++mf) {
        int r0 = row0 + wm * 64 + mf * 16 + grp;
        int r1 = r0 + 8;
#pragma unroll
        for (int nf = 0; nf < 4; ++nf) {
            int c = wn * 32 + nf * 8 + 2 * tg;
            float b0 = bias[c], b1 = bias[c + 1];
            if (r0 < N_NODES) {
                float2 o = make_float2(acc[mf][nf][0] + b0, acc[mf][nf][1] + b1);
                *reinterpret_cast<float2*>(outp + (size_t)r0 * LF + c) = o;
            }
            if (r1 < N_NODES) {
                float2 o = make_float2(acc[mf][nf][2] + b0, acc[mf][nf][3] + b1);
                *reinterpret_cast<float2*>(outp + (size_t)r1 * LF + c) = o;
            }
        }
    }
}

// ---------------- segment max pool over sorted batch ----------------------
__global__ void pool_kernel(const int* __restrict__ batch) {
    int g = blockIdx.x;
    int col = threadIdx.x;

    int lo = 0, hi = N_NODES;
    while (lo < hi) { int mid = (lo + hi) >> 1; if (batch[mid] < g) lo = mid + 1; else hi = mid; }
    int start = lo;
    hi = N_NODES;
    while (lo < hi) { int mid = (lo + hi) >> 1; if (batch[mid] < g + 1) lo = mid + 1; else hi = mid; }
    int end = lo;

    float m = -FLT_MAX;
    for (int r = start; r < end; ++r)
        m = fmaxf(m, g_hc[(size_t)r * LF + col]);
    g_pooled[g * LF + col] = m;
}

// ---------------- final MLP: relu(pooled@W1^T+b1)@W2^T+b2 -----------------
__global__ void mlp_kernel(const float* __restrict__ W1, const float* __restrict__ b1,
                           const float* __restrict__ W2, const float* __restrict__ b2,
                           float* __restrict__ out) {
    int g = blockIdx.x;
    int tid = threadIdx.x;

    __shared__ __align__(16) float p[LF];
    __shared__ __align__(16) float z[F];

    for (int i = tid; i < LF; i += F) p[i] = g_pooled[g * LF + i];
    __syncthreads();

    float s = b1[tid];
    const float* w = W1 + tid * LF;
#pragma unroll 4
    for (int k = 0; k < LF; k += 4) {
        float4 wv = *reinterpret_cast<const float4*>(w + k);
        s += wv.x * p[k] + wv.y * p[k + 1] + wv.z * p[k + 2] + wv.w * p[k + 3];
    }
    z[tid] = fmaxf(s, 0.f);
    __syncthreads();

    if (tid < T_OUT) {
        float o = b2[tid];
        const float* w2 = W2 + tid * F;
#pragma unroll 4
        for (int k = 0; k < F; k += 4) {
            float4 wv = *reinterpret_cast<const float4*>(w2 + k);
            o += wv.x * z[k] + wv.y * z[k + 1] + wv.z * z[k + 2] + wv.w * z[k + 3];
        }
        out[g * T_OUT + tid] = o;
    }
}

// ---------------- launch --------------------------------------------------
extern "C" void kernel_launch(void* const* d_in, const int* in_sizes, int n_in,
                              void* d_out, int out_size) {
    const float* x     = (const float*)d_in[0];
    const int*   ei    = (const int*)d_in[1];
    const int*   batch = (const int*)d_in[2];
    const float* Wl    = (const float*)d_in[3];
    const float* bl    = (const float*)d_in[4];
    const float* Wr    = (const float*)d_in[5];
    const float* W1    = (const float*)d_in[6];
    const float* b1    = (const float*)d_in[7];
    const float* W2    = (const float*)d_in[8];
    const float* b2    = (const float*)d_in[9];
    float* out = (float*)d_out;

    // CSR build (by dst)
    zero_deg_kernel<<<(N_NODES + 255) / 256, 256>>>();
    deg_kernel<<<(N_EDGES + 255) / 256, 256>>>(ei);
    scan_kernel<<<1, 1024>>>();
    fill_kernel<<<(N_EDGES + 255) / 256, 256>>>(ei);

    const int gather_blocks = (N_NODES * 32 + 255) / 256;  // 6250
    const int gemm_blocks   = (N_NODES + 127) / 128;       // 391

    for (int layer = 0; layer < L_LAYERS; ++layer) {
        gather_kernel<<<gather_blocks, 256>>>(x, layer);
        sage_gemm_tf32_kernel<<<gemm_blocks, 256>>>(x, layer, Wl, Wr, bl);
    }

    pool_kernel<<<G_GROUPS, LF>>>(batch);
    mlp_kernel<<<G_GROUPS, F>>>(W1, b1, W2, b2, out);
}

// round 6
// speedup vs baseline: 3.7521x; 1.2642x over previous
#include <cuda_runtime.h>
#include <float.h>
#include <stdint.h>

#define N_NODES 50000
#define N_EDGES 800000
#define F 128
#define L_LAYERS 3
#define G_GROUPS 256
#define T_OUT 10
#define LF (L_LAYERS * F)   // 384

#define SCAN_BLOCKS ((N_NODES + 255) / 256)   // 196

// ---------------- scratch (device globals; no allocation allowed) ----------
__device__ __align__(16) float g_agg[N_NODES * F];
__device__ __align__(16) float g_hc[N_NODES * LF];
__device__ __align__(16) int   g_deg[N_NODES];
__device__ __align__(16) int   g_row_start[N_NODES + 1];
__device__ __align__(16) int   g_cursor[N_NODES];
__device__ __align__(16) int   g_csr_src[N_EDGES];
__device__ __align__(16) int   g_bsum[SCAN_BLOCKS];
__device__ __align__(16) float g_pooled[G_GROUPS * LF];

// ---------------- CSR build -----------------------------------------------
__global__ void zero_deg_kernel() {
    int i = blockIdx.x * blockDim.x + threadIdx.x;
    if (i < N_NODES) g_deg[i] = 0;
}

__global__ void deg_kernel(const int* __restrict__ ei) {
    int e = blockIdx.x * blockDim.x + threadIdx.x;
    if (e < N_EDGES) {
        int d = ei[N_EDGES + e];
        if ((unsigned)d < N_NODES) atomicAdd(&g_deg[d], 1);
    }
}

// two-level scan: (1) per-block reduce, (2) scan block sums, (3) block scan+offset
__global__ void scan_reduce_kernel() {
    __shared__ int s[256];
    int tid = threadIdx.x;
    int idx = blockIdx.x * 256 + tid;
    s[tid] = (idx < N_NODES) ? g_deg[idx] : 0;
    __syncthreads();
#pragma unroll
    for (int off = 128; off > 0; off >>= 1) {
        if (tid < off) s[tid] += s[tid + off];
        __syncthreads();
    }
    if (tid == 0) g_bsum[blockIdx.x] = s[0];
}

__global__ void scan_bsum_kernel() {
    __shared__ int s[256];
    int tid = threadIdx.x;
    int v = (tid < SCAN_BLOCKS) ? g_bsum[tid] : 0;
    s[tid] = v;
    __syncthreads();
#pragma unroll
    for (int off = 1; off < 256; off <<= 1) {
        int t = (tid >= off) ? s[tid - off] : 0;
        __syncthreads();
        s[tid] += t;
        __syncthreads();
    }
    if (tid < SCAN_BLOCKS) g_bsum[tid] = s[tid] - v;   // exclusive
}

__global__ void scan_final_kernel() {
    __shared__ int s[256];
    int tid = threadIdx.x;
    int idx = blockIdx.x * 256 + tid;
    int v = (idx < N_NODES) ? g_deg[idx] : 0;
    s[tid] = v;
    __syncthreads();
#pragma unroll
    for (int off = 1; off < 256; off <<= 1) {
        int t = (tid >= off) ? s[tid - off] : 0;
        __syncthreads();
        s[tid] += t;
        __syncthreads();
    }
    if (idx < N_NODES) {
        int excl = g_bsum[blockIdx.x] + s[tid] - v;
        g_row_start[idx] = excl;
        g_cursor[idx] = excl;
        if (idx == N_NODES - 1) g_row_start[N_NODES] = N_EDGES;
    }
}

__global__ void fill_kernel(const int* __restrict__ ei) {
    int e = blockIdx.x * blockDim.x + threadIdx.x;
    if (e < N_EDGES) {
        int src = ei[e];
        int dst = ei[N_EDGES + e];
        if ((unsigned)src < N_NODES && (unsigned)dst < N_NODES) {
            int pos = atomicAdd(&g_cursor[dst], 1);
            g_csr_src[pos] = src;
        }
    }
}

// ---------------- per-node warp gather: agg[n] = mean_{s in N(n)} h[s] ----
__global__ void __launch_bounds__(256) gather_kernel(const float* __restrict__ x, int layer) {
    int gtid = blockIdx.x * blockDim.x + threadIdx.x;
    int node = gtid >> 5;
    int lane = gtid & 31;
    if (node >= N_NODES) return;

    const float* h;
    int stride;
    if (layer == 0) { h = x; stride = F; }
    else            { h = g_hc + (layer - 1) * F; stride = LF; }

    int start = g_row_start[node];
    int end   = g_row_start[node + 1];

    float4 acc = make_float4(0.f, 0.f, 0.f, 0.f);
    int i = start;
    for (; i + 4 <= end; i += 4) {
        int s0 = g_csr_src[i + 0];
        int s1 = g_csr_src[i + 1];
        int s2 = g_csr_src[i + 2];
        int s3 = g_csr_src[i + 3];
        float4 v0 = *reinterpret_cast<const float4*>(h + (size_t)s0 * stride + lane * 4);
        float4 v1 = *reinterpret_cast<const float4*>(h + (size_t)s1 * stride + lane * 4);
        float4 v2 = *reinterpret_cast<const float4*>(h + (size_t)s2 * stride + lane * 4);
        float4 v3 = *reinterpret_cast<const float4*>(h + (size_t)s3 * stride + lane * 4);
        acc.x += v0.x + v1.x + v2.x + v3.x;
        acc.y += v0.y + v1.y + v2.y + v3.y;
        acc.z += v0.z + v1.z + v2.z + v3.z;
        acc.w += v0.w + v1.w + v2.w + v3.w;
    }
    for (; i < end; ++i) {
        int s0 = g_csr_src[i];
        float4 v0 = *reinterpret_cast<const float4*>(h + (size_t)s0 * stride + lane * 4);
        acc.x += v0.x; acc.y += v0.y; acc.z += v0.z; acc.w += v0.w;
    }

    int d = end - start;
    float inv = d > 0 ? 1.0f / (float)d : 0.0f;
    acc.x *= inv; acc.y *= inv; acc.z *= inv; acc.w *= inv;
    *reinterpret_cast<float4*>(g_agg + (size_t)node * F + lane * 4) = acc;
}

// ---------------- TF32 tensor-core fused SAGE GEMM (BK=64, dyn smem) -------
// out[n,:] = agg[n,:] @ Wl^T + h[n,:] @ Wr^T + bl
// Block tile 128x128, 8 warps (2x4), warp tile 64x32, mma.m16n8k8.tf32.
#define BKT 64
#define ASTRIDE 68    // 68 mod 32 = 4 -> frag-load banks 4*grp+tg, conflict-free
#define BSTRIDE 136   // 136 mod 32 = 8 -> frag-load banks 8*tg+grp, conflict-free
#define A_WORDS (128 * ASTRIDE)          // 8704
#define B_WORDS (BKT * BSTRIDE)          // 8704
#define GEMM_SMEM_BYTES ((A_WORDS + B_WORDS) * 4)   // 69632

__device__ __forceinline__ uint32_t f2tf32(float f) {
    uint32_t u;
    asm volatile("cvt.rna.tf32.f32 %0, %1;" : "=r"(u) : "f"(f));
    return u;
}

__device__ __forceinline__ void mma_tf32(float* d,
                                         const uint32_t* a, const uint32_t* b) {
    asm volatile(
        "mma.sync.aligned.m16n8k8.row.col.f32.tf32.tf32.f32 "
        "{%0,%1,%2,%3}, {%4,%5,%6,%7}, {%8,%9}, {%0,%1,%2,%3};\n"
        : "+f"(d[0]), "+f"(d[1]), "+f"(d[2]), "+f"(d[3])
        : "r"(a[0]), "r"(a[1]), "r"(a[2]), "r"(a[3]),
          "r"(b[0]), "r"(b[1]));
}

__global__ void __launch_bounds__(256, 2) sage_gemm_tf32_kernel(
    const float* __restrict__ x, int layer,
    const float* __restrict__ Wl_all, const float* __restrict__ Wr_all,
    const float* __restrict__ bl_all) {

    extern __shared__ uint32_t smem[];
    uint32_t* As = smem;             // [128][ASTRIDE]
    uint32_t* Bs = smem + A_WORDS;   // [BKT][BSTRIDE]

    const float* Wl = Wl_all + layer * F * F;
    const float* Wr = Wr_all + layer * F * F;

    const float* h;
    int strideH;
    if (layer == 0) { h = x; strideH = F; }
    else            { h = g_hc + (layer - 1) * F; strideH = LF; }

    int tid  = threadIdx.x;
    int warp = tid >> 5;
    int lane = tid & 31;
    int wm = warp >> 2;          // 0..1
    int wn = warp & 3;           // 0..3
    int grp = lane >> 2;         // 0..7
    int tg  = lane & 3;          // 0..3

    int row0 = blockIdx.x * 128;

    float acc[4][4][4];
#pragma unroll
    for (int mf = 0; mf < 4; ++mf)
#pragma unroll
        for (int nf = 0; nf < 4; ++nf)
#pragma unroll
            for (int r = 0; r < 4; ++r) acc[mf][nf][r] = 0.f;

    for (int pass = 0; pass < 2; ++pass) {
        const float* A = pass ? h : g_agg;
        int sA = pass ? strideH : F;
        const float* W = pass ? Wr : Wl;

        for (int k0 = 0; k0 < F; k0 += BKT) {
            __syncthreads();   // protect previous stage's frag reads
            // ---- A stage: 128 rows x 64 cols; 2048 float4 slots ----
#pragma unroll
            for (int i = 0; i < 8; ++i) {
                int t4 = tid + i * 256;          // 0..2047
                int m  = t4 >> 4;                // 0..127
                int c4 = (t4 & 15) * 4;          // 0..60
                float4 v = make_float4(0.f, 0.f, 0.f, 0.f);
                int grow = row0 + m;
                if (grow < N_NODES)
                    v = *reinterpret_cast<const float4*>(A + (size_t)grow * sA + k0 + c4);
                uint32_t* dstp = &As[m * ASTRIDE + c4];
                dstp[0] = f2tf32(v.x);
                dstp[1] = f2tf32(v.y);
                dstp[2] = f2tf32(v.z);
                dstp[3] = f2tf32(v.w);
            }
            // ---- B stage: Bs[k][j] = W[j*F + k0 + k], k 0..63, j 0..127 ----
#pragma unroll
            for (int i = 0; i < 8; ++i) {
                int t4 = tid + i * 256;
                int j  = t4 & 127;
                int c4 = (t4 >> 7) * 4;          // 0..60
                float4 w = *reinterpret_cast<const float4*>(W + j * F + k0 + c4);
                Bs[(c4 + 0) * BSTRIDE + j] = f2tf32(w.x);
                Bs[(c4 + 1) * BSTRIDE + j] = f2tf32(w.y);
                Bs[(c4 + 2) * BSTRIDE + j] = f2tf32(w.z);
                Bs[(c4 + 3) * BSTRIDE + j] = f2tf32(w.w);
            }
            __syncthreads();

#pragma unroll
            for (int kk = 0; kk < BKT; kk += 8) {
                uint32_t afr[4][4], bfr[4][2];
#pragma unroll
                for (int mf = 0; mf < 4; ++mf) {
                    int mr = wm * 64 + mf * 16 + grp;
                    afr[mf][0] = As[mr * ASTRIDE + kk + tg];
                    afr[mf][1] = As[(mr + 8) * ASTRIDE + kk + tg];
                    afr[mf][2] = As[mr * ASTRIDE + kk + tg + 4];
                    afr[mf][3] = As[(mr + 8) * ASTRIDE + kk + tg + 4];
                }
#pragma unroll
                for (int nf = 0; nf < 4; ++nf) {
                    int nc = wn * 32 + nf * 8 + grp;
                    bfr[nf][0] = Bs[(kk + tg) * BSTRIDE + nc];
                    bfr[nf][1] = Bs[(kk + tg + 4) * BSTRIDE + nc];
                }
#pragma unroll
                for (int mf = 0; mf < 4; ++mf)
#pragma unroll
                    for (int nf = 0; nf < 4; ++nf)
                        mma_tf32(acc[mf][nf], afr[mf], bfr[nf]);
            }
        }
    }

    // ---- epilogue: + bias, write hc[:, layer*F : (layer+1)*F] ----
    const float* bias = bl_all + layer * F;
    float* outp = g_hc + layer * F;
#pragma unroll
    for (int mf = 0; mf < 4; ++mf) {
        int r0 = row0 + wm * 64 + mf * 16 + grp;
        int r1 = r0 + 8;
#pragma unroll
        for (int nf = 0; nf < 4; ++nf) {
            int c = wn * 32 + nf * 8 + 2 * tg;
            float b0 = bias[c], b1 = bias[c + 1];
            if (r0 < N_NODES) {
                float2 o = make_float2(acc[mf][nf][0] + b0, acc[mf][nf][1] + b1);
                *reinterpret_cast<float2*>(outp + (size_t)r0 * LF + c) = o;
            }
            if (r1 < N_NODES) {
                float2 o = make_float2(acc[mf][nf][2] + b0, acc[mf][nf][3] + b1);
                *reinterpret_cast<float2*>(outp + (size_t)r1 * LF + c) = o;
            }
        }
    }
}

// ---------------- segment max pool over sorted batch ----------------------
__global__ void pool_kernel(const int* __restrict__ batch) {
    int g = blockIdx.x;
    int col = threadIdx.x;

    int lo = 0, hi = N_NODES;
    while (lo < hi) { int mid = (lo + hi) >> 1; if (batch[mid] < g) lo = mid + 1; else hi = mid; }
    int start = lo;
    hi = N_NODES;
    while (lo < hi) { int mid = (lo + hi) >> 1; if (batch[mid] < g + 1) lo = mid + 1; else hi = mid; }
    int end = lo;

    float m = -FLT_MAX;
    for (int r = start; r < end; ++r)
        m = fmaxf(m, g_hc[(size_t)r * LF + col]);
    g_pooled[g * LF + col] = m;
}

// ---------------- final MLP: relu(pooled@W1^T+b1)@W2^T+b2 -----------------
__global__ void mlp_kernel(const float* __restrict__ W1, const float* __restrict__ b1,
                           const float* __restrict__ W2, const float* __restrict__ b2,
                           float* __restrict__ out) {
    int g = blockIdx.x;
    int tid = threadIdx.x;

    __shared__ __align__(16) float p[LF];
    __shared__ __align__(16) float z[F];

    for (int i = tid; i < LF; i += F) p[i] = g_pooled[g * LF + i];
    __syncthreads();

    float s = b1[tid];
    const float* w = W1 + tid * LF;
#pragma unroll 4
    for (int k = 0; k < LF; k += 4) {
        float4 wv = *reinterpret_cast<const float4*>(w + k);
        s += wv.x * p[k] + wv.y * p[k + 1] + wv.z * p[k + 2] + wv.w * p[k + 3];
    }
    z[tid] = fmaxf(s, 0.f);
    __syncthreads();

    if (tid < T_OUT) {
        float o = b2[tid];
        const float* w2 = W2 + tid * F;
#pragma unroll 4
        for (int k = 0; k < F; k += 4) {
            float4 wv = *reinterpret_cast<const float4*>(w2 + k);
            o += wv.x * z[k] + wv.y * z[k + 1] + wv.z * z[k + 2] + wv.w * z[k + 3];
        }
        out[g * T_OUT + tid] = o;
    }
}

// ---------------- launch --------------------------------------------------
extern "C" void kernel_launch(void* const* d_in, const int* in_sizes, int n_in,
                              void* d_out, int out_size) {
    const float* x     = (const float*)d_in[0];
    const int*   ei    = (const int*)d_in[1];
    const int*   batch = (const int*)d_in[2];
    const float* Wl    = (const float*)d_in[3];
    const float* bl    = (const float*)d_in[4];
    const float* Wr    = (const float*)d_in[5];
    const float* W1    = (const float*)d_in[6];
    const float* b1    = (const float*)d_in[7];
    const float* W2    = (const float*)d_in[8];
    const float* b2    = (const float*)d_in[9];
    float* out = (float*)d_out;

    static bool attr_set = false;
    if (!attr_set) {
        cudaFuncSetAttribute(sage_gemm_tf32_kernel,
                             cudaFuncAttributeMaxDynamicSharedMemorySize,
                             GEMM_SMEM_BYTES);
        attr_set = true;
    }

    // CSR build (by dst)
    zero_deg_kernel<<<(N_NODES + 255) / 256, 256>>>();
    deg_kernel<<<(N_EDGES + 255) / 256, 256>>>(ei);
    scan_reduce_kernel<<<SCAN_BLOCKS, 256>>>();
    scan_bsum_kernel<<<1, 256>>>();
    scan_final_kernel<<<SCAN_BLOCKS, 256>>>();
    fill_kernel<<<(N_EDGES + 255) / 256, 256>>>(ei);

    const int gather_blocks = (N_NODES * 32 + 255) / 256;  // 6250
    const int gemm_blocks   = (N_NODES + 127) / 128;       // 391

    for (int layer = 0; layer < L_LAYERS; ++layer) {
        gather_kernel<<<gather_blocks, 256>>>(x, layer);
        sage_gemm_tf32_kernel<<<gemm_blocks, 256, GEMM_SMEM_BYTES>>>(x, layer, Wl, Wr, bl);
    }

    pool_kernel<<<G_GROUPS, LF>>>(batch);
    mlp_kernel<<<G_GROUPS, F>>>(W1, b1, W2, b2, out);
}